// round 2
// baseline (speedup 1.0000x reference)
#include <cuda_runtime.h>
#include <cuda_bf16.h>
#include <math.h>

// ---------------- problem constants ----------------
#define NB    4
#define CIN   64
#define CR    32
#define HH    96
#define WW    96
#define HWQ   (HH*WW)        // 9216 queries per sample
#define HS    48
#define WS    48
#define LKEY  (HS*WS)        // 2304 keys per sample
#define KF    (CR*9)         // 288 q/k feature dim
#define VF    (CIN*9)        // 576 value dim (j = tap*64 + c)
#define OH    191

// ---------------- scratch (device globals; allocation-free) ----------------
__device__ float g_match[(size_t)NB*CR*98*98];          // padded match_input
__device__ float g_embed[(size_t)NB*CIN*50*50];         // padded embed_w
__device__ float g_ref  [(size_t)NB*CR*50*50];          // padded ref
__device__ float g_Q [(size_t)NB*KF*HWQ];               // [b][f][m]
__device__ float g_KT[(size_t)NB*KF*LKEY];              // [b][f][l]  (SCALE/norm folded)
__device__ float g_V [(size_t)NB*LKEY*VF];              // [b][l][j]  (/6 folded)
__device__ float g_S [(size_t)NB*LKEY*HWQ];             // logits -> exp(P)  (340MB)
__device__ float g_U [(size_t)NB*VF*HWQ];               // [b][j][q]  (85MB, transposed)
__device__ float g_qmax[NB*HWQ];
__device__ float g_invs[NB*HWQ];

// ---------------- helpers ----------------
__device__ __forceinline__ void fma2(unsigned long long& d,
                                     unsigned long long a,
                                     unsigned long long b) {
    asm("fma.rn.f32x2 %0, %1, %2, %0;" : "+l"(d) : "l"(a), "l"(b));
}

// ---------------- zero the padded buffers ----------------
__global__ void zero_pads() {
    int i = blockIdx.x * blockDim.x + threadIdx.x;
    constexpr int n1 = NB*CR*98*98;
    constexpr int n2 = NB*CIN*50*50;
    constexpr int n3 = NB*CR*50*50;
    if (i < n1) g_match[i] = 0.f;
    if (i < n2) g_embed[i] = 0.f;
    if (i < n3) g_ref[i]   = 0.f;
}

// ---------------- conv1x1 + prelu -> padded buffer ----------------
// SEL 0: input -> g_match (Cout=32, 96x96 -> 98x98)
// SEL 1: small -> g_embed (Cout=64, 48x48 -> 50x50)
// SEL 2: small -> g_ref   (Cout=32, 48x48 -> 50x50)
template<int SEL>
__global__ void conv1x1_prelu(const float* __restrict__ in,
                              const float* __restrict__ w,
                              const float* __restrict__ bias,
                              const float* __restrict__ a) {
    constexpr int HWd  = (SEL == 0) ? HWQ : LKEY;
    constexpr int Wd   = (SEL == 0) ? WW : WS;
    constexpr int Wp   = (SEL == 0) ? 98 : 50;
    constexpr int Cout = (SEL == 1) ? CIN : CR;
    float* outp = (SEL == 0) ? g_match : ((SEL == 1) ? g_embed : g_ref);

    int px = blockIdx.x * blockDim.x + threadIdx.x;
    int co = blockIdx.y, b = blockIdx.z;
    const float* ip = in + (size_t)b * CIN * HWd + px;
    const float* wp = w + co * CIN;
    float s = bias[co];
#pragma unroll 16
    for (int ci = 0; ci < CIN; ++ci) s = fmaf(ip[(size_t)ci * HWd], wp[ci], s);
    float al = a[0];
    s = (s >= 0.f) ? s : al * s;
    int y = px / Wd, x = px - y * Wd;
    outp[((size_t)(b * Cout + co) * Wp + (y + 1)) * Wp + (x + 1)] = s;
}

// ---------------- build Q: [b][f][m] from padded match ----------------
__global__ void build_Q() {
    int m = blockIdx.x * blockDim.x + threadIdx.x;     // 9216
    int f = blockIdx.y, b = blockIdx.z;
    int c = f / 9, t = f - 9 * c;
    int ky = t / 3, kx = t - 3 * ky;
    int y = m / WW, x = m - y * WW;
    g_Q[((size_t)b * KF + f) * HWQ + m] =
        g_match[(((size_t)b * CR + c) * 98 + y + ky) * 98 + x + kx];
}

// ---------------- build K^T: [b][f][l], normalized, x SCALE ----------------
__global__ void build_KT() {
    int l = blockIdx.x * blockDim.x + threadIdx.x;     // 2304
    int b = blockIdx.y;
    int ly = l / WS, lx = l - WS * ly;
    const float* base = g_ref + (size_t)b * CR * 2500;
    float ss = 0.f;
    for (int c = 0; c < CR; ++c) {
#pragma unroll
        for (int t = 0; t < 9; ++t) {
            float v = base[((size_t)c * 50 + ly + t / 3) * 50 + lx + t % 3];
            ss = fmaf(v, v, ss);
        }
    }
    float sc = 10.0f / fmaxf(sqrtf(ss), 1e-4f);        // SCALE / max(norm, EPS)
    for (int c = 0; c < CR; ++c) {
#pragma unroll
        for (int t = 0; t < 9; ++t) {
            float v = base[((size_t)c * 50 + ly + t / 3) * 50 + lx + t % 3];
            g_KT[((size_t)b * KF + (c * 9 + t)) * LKEY + l] = v * sc;
        }
    }
}

// ---------------- build V: [b][l][t*64+c], /6 folded ----------------
__global__ void build_V() {
    int c = threadIdx.x;                               // 64
    int l = blockIdx.x, b = blockIdx.y;
    int ly = l / WS, lx = l - WS * ly;
    const float* base = g_embed + ((size_t)b * CIN + c) * 2500;
    float* vp = g_V + ((size_t)b * LKEY + l) * VF;
#pragma unroll
    for (int t = 0; t < 9; ++t)
        vp[t * 64 + c] = base[(ly + t / 3) * 50 + lx + t % 3] * (1.0f / 6.0f);
}

// ---------------- FFMA2 tiled GEMM ----------------
// PHASE 1: C[m][n] = A^T(KT)[K=288][M=2304] x B(Q)[288][N=9216]   -> g_S [key][query]
// PHASE 2: C[n][m] = A^T(S) [K=2304][M=9216] x B(V)[2304][N=576]  -> g_U [j][query]
template<int PHASE>
__global__ __launch_bounds__(256, 4) void gemm_kernel() {
    constexpr int M = (PHASE == 1) ? LKEY : HWQ;
    constexpr int N = (PHASE == 1) ? HWQ  : VF;
    constexpr int K = (PHASE == 1) ? KF   : LKEY;
    const float* __restrict__ Abase = (PHASE == 1) ? g_KT : g_S;
    const float* __restrict__ Bbase = (PHASE == 1) ? g_Q  : g_V;
    float* __restrict__ Cbase       = (PHASE == 1) ? g_S  : g_U;

    __shared__ float As[32 * 128];   // k-major, m duplicated pairs, 16B xor-swizzle on odd k
    __shared__ float Bs[32 * 64];    // k-major, n contiguous

    int b = blockIdx.z;
    const float* Ag = Abase + (size_t)b * K * M;
    const float* Bg = Bbase + (size_t)b * K * N;
    int n0 = blockIdx.x * 64, m0 = blockIdx.y * 64;
    int tid = threadIdx.x;
    int tx = tid & 15, ty = tid >> 4;

    unsigned long long acc[4][2];
#pragma unroll
    for (int i = 0; i < 4; ++i)
#pragma unroll
        for (int j = 0; j < 2; ++j) acc[i][j] = 0ull;

    int kk0 = tid >> 4, q0 = tid & 15;        // item tid
    int kk1 = (tid + 256) >> 4;               // item tid+256 (same q)

    for (int kt = 0; kt < K; kt += 32) {
        float4 a0 = *(const float4*)(Ag + (size_t)(kt + kk0) * M + m0 + q0 * 4);
        float4 a1 = *(const float4*)(Ag + (size_t)(kt + kk1) * M + m0 + q0 * 4);
        float4 b0 = *(const float4*)(Bg + (size_t)(kt + kk0) * N + n0 + q0 * 4);
        float4 b1 = *(const float4*)(Bg + (size_t)(kt + kk1) * N + n0 + q0 * 4);
        __syncthreads();
        {
            int sw0 = (kk0 & 1) * 4;
            *(float4*)(As + kk0 * 128 + ((q0 * 8) ^ sw0))       = make_float4(a0.x, a0.x, a0.y, a0.y);
            *(float4*)(As + kk0 * 128 + ((q0 * 8 + 4) ^ sw0))   = make_float4(a0.z, a0.z, a0.w, a0.w);
            int sw1 = (kk1 & 1) * 4;
            *(float4*)(As + kk1 * 128 + ((q0 * 8) ^ sw1))       = make_float4(a1.x, a1.x, a1.y, a1.y);
            *(float4*)(As + kk1 * 128 + ((q0 * 8 + 4) ^ sw1))   = make_float4(a1.z, a1.z, a1.w, a1.w);
            *(float4*)(Bs + kk0 * 64 + q0 * 4) = b0;
            *(float4*)(Bs + kk1 * 64 + q0 * 4) = b1;
        }
        __syncthreads();
#pragma unroll
        for (int kk = 0; kk < 32; ++kk) {
            int sw = (kk & 1) * 4;
            const float* ar = As + kk * 128;
            const float* br = Bs + kk * 64;
            unsigned long long av[4], bv[2];
#pragma unroll
            for (int i = 0; i < 4; ++i) {
                int mm = ty + 16 * i;
                av[i] = *(const unsigned long long*)(ar + ((2 * mm) ^ sw));
            }
#pragma unroll
            for (int j = 0; j < 2; ++j)
                bv[j] = *(const unsigned long long*)(br + 2 * (tx + 16 * j));
#pragma unroll
            for (int i = 0; i < 4; ++i)
#pragma unroll
                for (int j = 0; j < 2; ++j) fma2(acc[i][j], av[i], bv[j]);
        }
    }

    float* Cg = Cbase + (size_t)b * M * N;
    if (PHASE == 1) {
#pragma unroll
        for (int i = 0; i < 4; ++i) {
            int m = m0 + ty + 16 * i;
#pragma unroll
            for (int j = 0; j < 2; ++j) {
                int n = n0 + 2 * (tx + 16 * j);
                *(unsigned long long*)(Cg + (size_t)m * N + n) = acc[i][j];
            }
        }
    } else {
#pragma unroll
        for (int i = 0; i < 4; ++i) {
            int m = m0 + ty + 16 * i;
#pragma unroll
            for (int j = 0; j < 2; ++j) {
                int n = n0 + 2 * (tx + 16 * j);
                float2 v = *reinterpret_cast<float2*>(&acc[i][j]);
                Cg[(size_t)n * M + m]       = v.x;
                Cg[(size_t)(n + 1) * M + m] = v.y;
            }
        }
    }
}

// ---------------- column max over keys ----------------
__global__ void colmax_kernel() {
    int q = blockIdx.x * blockDim.x + threadIdx.x;
    int b = blockIdx.y;
    const float* sp = g_S + (size_t)b * LKEY * HWQ + q;
    float m0 = -1e30f, m1 = -1e30f, m2 = -1e30f, m3 = -1e30f;
    for (int k = 0; k < LKEY; k += 4) {
        m0 = fmaxf(m0, sp[(size_t)(k + 0) * HWQ]);
        m1 = fmaxf(m1, sp[(size_t)(k + 1) * HWQ]);
        m2 = fmaxf(m2, sp[(size_t)(k + 2) * HWQ]);
        m3 = fmaxf(m3, sp[(size_t)(k + 3) * HWQ]);
    }
    g_qmax[b * HWQ + q] = fmaxf(fmaxf(m0, m1), fmaxf(m2, m3));
}

// ---------------- exp (unnormalized) + inv-sum ----------------
__global__ void expsum_kernel() {
    int q = blockIdx.x * blockDim.x + threadIdx.x;
    int b = blockIdx.y;
    float mx = g_qmax[b * HWQ + q];
    float* sp = g_S + (size_t)b * LKEY * HWQ + q;
    float s0 = 0.f, s1 = 0.f, s2 = 0.f, s3 = 0.f;
    for (int k = 0; k < LKEY; k += 4) {
        float x0 = sp[(size_t)(k + 0) * HWQ];
        float x1 = sp[(size_t)(k + 1) * HWQ];
        float x2 = sp[(size_t)(k + 2) * HWQ];
        float x3 = sp[(size_t)(k + 3) * HWQ];
        float e0 = __expf(x0 - mx);
        float e1 = __expf(x1 - mx);
        float e2 = __expf(x2 - mx);
        float e3 = __expf(x3 - mx);
        sp[(size_t)(k + 0) * HWQ] = e0;
        sp[(size_t)(k + 1) * HWQ] = e1;
        sp[(size_t)(k + 2) * HWQ] = e2;
        sp[(size_t)(k + 3) * HWQ] = e3;
        s0 += e0; s1 += e1; s2 += e2; s3 += e3;
    }
    g_invs[b * HWQ + q] = 1.0f / (s0 + s1 + s2 + s3);
}

// ---------------- parity-plane gather: U -> out ----------------
// out[b][c][oy][ox] = sum over contributing (y,ty),(x,tx):
//   U[b][(ty*3+tx)*64+c][y*96+x] * invs[b][y*96+x]
__global__ void gather_out(float* __restrict__ out) {
    int ox = blockIdx.x * blockDim.x + threadIdx.x;
    if (ox >= OH) return;
    int oy = blockIdx.y;
    int bc = blockIdx.z;
    int b = bc >> 6, c = bc & 63;

    int ys[2], tys[2], ny;
    if (oy & 1) { ny = 2; ys[0] = (oy - 1) >> 1; tys[0] = 2; ys[1] = (oy + 1) >> 1; tys[1] = 0; }
    else        { ny = 1; ys[0] = oy >> 1; tys[0] = 1; }
    int xs[2], txs[2], nx;
    if (ox & 1) { nx = 2; xs[0] = (ox - 1) >> 1; txs[0] = 2; xs[1] = (ox + 1) >> 1; txs[1] = 0; }
    else        { nx = 1; xs[0] = ox >> 1; txs[0] = 1; }

    const float* Ub = g_U + (size_t)b * VF * HWQ;
    const float* is = g_invs + b * HWQ;
    float acc = 0.f;
    for (int iy = 0; iy < ny; ++iy)
        for (int ix = 0; ix < nx; ++ix) {
            int q = ys[iy] * WW + xs[ix];
            int t = tys[iy] * 3 + txs[ix];
            acc = fmaf(Ub[(size_t)(t * 64 + c) * HWQ + q], is[q], acc);
        }
    out[(((size_t)b * CIN + c) * OH + oy) * OH + ox] = acc;
}

// ---------------- launch ----------------
extern "C" void kernel_launch(void* const* d_in, const int* in_sizes, int n_in,
                              void* d_out, int out_size) {
    const float* input = (const float*)d_in[0];
    const float* small = (const float*)d_in[1];
    const float* w1 = (const float*)d_in[2];
    const float* b1 = (const float*)d_in[3];
    const float* a1 = (const float*)d_in[4];
    const float* w2 = (const float*)d_in[5];
    const float* b2 = (const float*)d_in[6];
    const float* a2 = (const float*)d_in[7];
    const float* wa = (const float*)d_in[8];
    const float* ba = (const float*)d_in[9];
    const float* aa = (const float*)d_in[10];
    float* out = (float*)d_out;

    zero_pads<<<(NB*CR*98*98 + 255) / 256, 256>>>();

    conv1x1_prelu<0><<<dim3(HWQ / 256, CR,  NB), 256>>>(input, w1, b1, a1);
    conv1x1_prelu<1><<<dim3(LKEY / 256, CIN, NB), 256>>>(small, wa, ba, aa);
    conv1x1_prelu<2><<<dim3(LKEY / 256, CR,  NB), 256>>>(small, w2, b2, a2);

    build_Q <<<dim3(HWQ / 256, KF, NB), 256>>>();
    build_KT<<<dim3(LKEY / 128, NB), 128>>>();
    build_V <<<dim3(LKEY, NB), 64>>>();

    gemm_kernel<1><<<dim3(HWQ / 64, LKEY / 64, NB), 256>>>();   // logits

    colmax_kernel<<<dim3(HWQ / 256, NB), 256>>>();
    expsum_kernel<<<dim3(HWQ / 256, NB), 256>>>();

    gemm_kernel<2><<<dim3(VF / 64, HWQ / 64, NB), 256>>>();     // U = P x V (transposed out)

    gather_out<<<dim3((OH + 127) / 128, OH, NB * CIN), 128>>>(out);
}

// round 8
// speedup vs baseline: 1.2364x; 1.2364x over previous
#include <cuda_runtime.h>
#include <cuda_bf16.h>
#include <math.h>

// ---------------- problem constants ----------------
#define NB    4
#define CIN   64
#define CR    32
#define HH    96
#define WW    96
#define HWQ   (HH*WW)        // 9216 queries per sample
#define HS    48
#define WS    48
#define LKEY  (HS*WS)        // 2304 keys per sample
#define KF    (CR*9)         // 288 q/k feature dim
#define VF    (CIN*9)        // 576 value dim (j = tap*64 + c)
#define OH    191

// ---------------- scratch (device globals; allocation-free) ----------------
__device__ float g_match[(size_t)NB*CR*98*98];          // padded match_input
__device__ float g_embed[(size_t)NB*CIN*50*50];         // padded embed_w
__device__ float g_ref  [(size_t)NB*CR*50*50];          // padded ref
__device__ float g_Q [(size_t)NB*KF*HWQ];               // [b][f][q]
__device__ float g_KT[(size_t)NB*KF*LKEY];              // [b][f][l]  (SCALE/norm folded)
__device__ float g_V [(size_t)NB*LKEY*VF];              // [b][l][j]  (/6 folded)
__device__ float g_S [(size_t)NB*LKEY*HWQ];             // exp(logit - qb)  (340MB)
__device__ float g_U [(size_t)NB*VF*HWQ];               // [b][j][q]
__device__ float g_qb  [NB*HWQ];                        // 10*||q_patch||
__device__ float g_sums[NB*HWQ];                        // column sums of exp
__device__ float g_invs[NB*HWQ];

// ---------------- helpers ----------------
__device__ __forceinline__ void fma2(unsigned long long& d,
                                     unsigned long long a,
                                     unsigned long long b) {
    asm("fma.rn.f32x2 %0, %1, %2, %0;" : "+l"(d) : "l"(a), "l"(b));
}

// ---------------- conv1x1 + prelu -> padded buffer (borders zeroed in-kernel) ----
// SEL 0: input -> g_match (Cout=32, 96x96 -> 98x98), also zeroes g_sums
// SEL 1: small -> g_embed (Cout=64, 48x48 -> 50x50)
// SEL 2: small -> g_ref   (Cout=32, 48x48 -> 50x50)
template<int SEL>
__global__ void conv1x1_prelu(const float* __restrict__ in,
                              const float* __restrict__ w,
                              const float* __restrict__ bias,
                              const float* __restrict__ a) {
    constexpr int HWd  = (SEL == 0) ? HWQ : LKEY;
    constexpr int Wd   = (SEL == 0) ? WW : WS;
    constexpr int Wp   = (SEL == 0) ? 98 : 50;
    constexpr int Cout = (SEL == 1) ? CIN : CR;
    constexpr int NBORD = (SEL == 0) ? 388 : 196;  // Wp*Wp - Wd*Wd
    float* outp = (SEL == 0) ? g_match : ((SEL == 1) ? g_embed : g_ref);

    int px = blockIdx.x * blockDim.x + threadIdx.x;
    int co = blockIdx.y, b = blockIdx.z;
    float* plane = outp + (size_t)(b * Cout + co) * Wp * Wp;

    // border zeroing (px enumerates border cells)
    if (px < NBORD) {
        int by, bx;
        if (px < Wp)            { by = 0;           bx = px; }
        else if (px < 2*Wp)     { by = Wp - 1;      bx = px - Wp; }
        else if (px < 2*Wp+Wd)  { by = px - 2*Wp + 1; bx = 0; }
        else                    { by = px - (2*Wp+Wd) + 1; bx = Wp - 1; }
        plane[by * Wp + bx] = 0.f;
    }
    if (SEL == 0 && co == 0) g_sums[b * HWQ + px] = 0.f;

    const float* ip = in + (size_t)b * CIN * HWd + px;
    const float* wp = w + co * CIN;
    float s = bias[co];
#pragma unroll 16
    for (int ci = 0; ci < CIN; ++ci) s = fmaf(ip[(size_t)ci * HWd], wp[ci], s);
    float al = a[0];
    s = (s >= 0.f) ? s : al * s;
    int y = px / Wd, x = px - y * Wd;
    plane[(y + 1) * Wp + (x + 1)] = s;
}

// ---------------- build Q: [b][f][q] from padded match ----------------
__global__ void build_Q() {
    int m = blockIdx.x * blockDim.x + threadIdx.x;     // 9216
    int f = blockIdx.y, b = blockIdx.z;
    int c = f / 9, t = f - 9 * c;
    int ky = t / 3, kx = t - 3 * ky;
    int y = m / WW, x = m - y * WW;
    g_Q[((size_t)b * KF + f) * HWQ + m] =
        g_match[(((size_t)b * CR + c) * 98 + y + ky) * 98 + x + kx];
}

// ---------------- build K^T: [b][f][l], normalized, x SCALE ----------------
__global__ void build_KT() {
    int l = blockIdx.x * blockDim.x + threadIdx.x;     // 2304
    int b = blockIdx.y;
    int ly = l / WS, lx = l - WS * ly;
    const float* base = g_ref + (size_t)b * CR * 2500;
    float ss = 0.f;
    for (int c = 0; c < CR; ++c) {
#pragma unroll
        for (int t = 0; t < 9; ++t) {
            float v = base[((size_t)c * 50 + ly + t / 3) * 50 + lx + t % 3];
            ss = fmaf(v, v, ss);
        }
    }
    float sc = 10.0f / fmaxf(sqrtf(ss), 1e-4f);        // SCALE / max(norm, EPS)
    for (int c = 0; c < CR; ++c) {
#pragma unroll
        for (int t = 0; t < 9; ++t) {
            float v = base[((size_t)c * 50 + ly + t / 3) * 50 + lx + t % 3];
            g_KT[((size_t)b * KF + (c * 9 + t)) * LKEY + l] = v * sc;
        }
    }
}

// ---------------- qb = 10*||q_patch|| (softmax shift; logit - qb <= 0) -----
__global__ void qbound_kernel() {
    int q = blockIdx.x * blockDim.x + threadIdx.x;     // 9216
    int b = blockIdx.y;
    int y = q / WW, x = q - y * WW;
    const float* base = g_match + (size_t)b * CR * 98 * 98;
    float ss = 0.f;
    for (int c = 0; c < CR; ++c) {
        const float* p = base + ((size_t)c * 98 + y) * 98 + x;
#pragma unroll
        for (int t = 0; t < 9; ++t) {
            float v = p[(t / 3) * 98 + (t % 3)];
            ss = fmaf(v, v, ss);
        }
    }
    g_qb[b * HWQ + q] = 10.0f * sqrtf(ss);
}

// ---------------- build V: [b][l][t*64+c], /6 folded ----------------
__global__ void build_V() {
    int c = threadIdx.x;                               // 64
    int l = blockIdx.x, b = blockIdx.y;
    int ly = l / WS, lx = l - WS * ly;
    const float* base = g_embed + ((size_t)b * CIN + c) * 2500;
    float* vp = g_V + ((size_t)b * LKEY + l) * VF;
#pragma unroll
    for (int t = 0; t < 9; ++t)
        vp[t * 64 + c] = base[(ly + t / 3) * 50 + lx + t % 3] * (1.0f / 6.0f);
}

// ---------------- FFMA2 tiled GEMM, 128x64 tile, BK=32, reg prefetch -------
// PHASE 1: C[m][n] = KT^T x Q : A[K=288][M=2304], B[288][N=9216] -> exp -> g_S
// PHASE 2: C[n][m] = S^T x V  : A[K=2304][M=9216], B[2304][N=576] -> g_U [j][q]
#define ASTR 264
#define BSTR 68
template<int PHASE>
__global__ __launch_bounds__(256, 2) void gemm_kernel() {
    constexpr int M = (PHASE == 1) ? LKEY : HWQ;
    constexpr int N = (PHASE == 1) ? HWQ  : VF;
    constexpr int K = (PHASE == 1) ? KF   : LKEY;
    const float* __restrict__ Abase = (PHASE == 1) ? g_KT : g_S;
    const float* __restrict__ Bbase = (PHASE == 1) ? g_Q  : g_V;
    float* __restrict__ Cbase       = (PHASE == 1) ? g_S  : g_U;

    __shared__ float As[32 * ASTR];     // k-major, m duplicated pairs
    __shared__ float Bs[32 * BSTR];     // k-major, n contiguous
    __shared__ float2 red[256][2];      // phase-1 column-sum reduction

    int b = blockIdx.z;
    const float* Ag = Abase + (size_t)b * K * M;
    const float* Bg = Bbase + (size_t)b * K * N;
    int n0 = blockIdx.x * 64, m0 = blockIdx.y * 128;
    int tid = threadIdx.x;
    int tx = tid & 15, ty = tid >> 4;

    // loader coords
    int lk = tid >> 3, lc = tid & 7;    // 32 k-rows x 8 col-groups

    unsigned long long acc[8][2];
#pragma unroll
    for (int i = 0; i < 8; ++i) { acc[i][0] = 0ull; acc[i][1] = 0ull; }

    float4 ra[4], rb[2];

    // prologue: tile 0
#pragma unroll
    for (int p = 0; p < 4; ++p)
        ra[p] = *(const float4*)(Ag + (size_t)lk * M + m0 + (lc + 8 * p) * 4);
#pragma unroll
    for (int p = 0; p < 2; ++p)
        rb[p] = *(const float4*)(Bg + (size_t)lk * N + n0 + (lc + 8 * p) * 4);
#pragma unroll
    for (int p = 0; p < 4; ++p) {
        int m4 = (lc + 8 * p) * 4;
        *(float4*)(As + lk * ASTR + m4 * 2)     = make_float4(ra[p].x, ra[p].x, ra[p].y, ra[p].y);
        *(float4*)(As + lk * ASTR + m4 * 2 + 4) = make_float4(ra[p].z, ra[p].z, ra[p].w, ra[p].w);
    }
#pragma unroll
    for (int p = 0; p < 2; ++p)
        *(float4*)(Bs + lk * BSTR + (lc + 8 * p) * 4) = rb[p];
    __syncthreads();

    for (int kt = 0; kt < K; kt += 32) {
        if (kt + 32 < K) {
#pragma unroll
            for (int p = 0; p < 4; ++p)
                ra[p] = *(const float4*)(Ag + (size_t)(kt + 32 + lk) * M + m0 + (lc + 8 * p) * 4);
#pragma unroll
            for (int p = 0; p < 2; ++p)
                rb[p] = *(const float4*)(Bg + (size_t)(kt + 32 + lk) * N + n0 + (lc + 8 * p) * 4);
        }
#pragma unroll
        for (int kk = 0; kk < 32; ++kk) {
            const float* ar = As + kk * ASTR;
            const float* br = Bs + kk * BSTR;
            unsigned long long av[8], bv[2];
#pragma unroll
            for (int j = 0; j < 2; ++j)
                bv[j] = *(const unsigned long long*)(br + 2 * (tx + 16 * j));
#pragma unroll
            for (int i = 0; i < 8; ++i)
                av[i] = *(const unsigned long long*)(ar + 2 * (ty + 16 * i));
#pragma unroll
            for (int i = 0; i < 8; ++i) {
                fma2(acc[i][0], av[i], bv[0]);
                fma2(acc[i][1], av[i], bv[1]);
            }
        }
        if (kt + 32 < K) {
            __syncthreads();
#pragma unroll
            for (int p = 0; p < 4; ++p) {
                int m4 = (lc + 8 * p) * 4;
                *(float4*)(As + lk * ASTR + m4 * 2)     = make_float4(ra[p].x, ra[p].x, ra[p].y, ra[p].y);
                *(float4*)(As + lk * ASTR + m4 * 2 + 4) = make_float4(ra[p].z, ra[p].z, ra[p].w, ra[p].w);
            }
#pragma unroll
            for (int p = 0; p < 2; ++p)
                *(float4*)(Bs + lk * BSTR + (lc + 8 * p) * 4) = rb[p];
            __syncthreads();
        }
    }

    float* Cg = Cbase + (size_t)b * M * N;
    if (PHASE == 1) {
        // exp(logit - qb), store, and column-sum via smem reduce + atomics
        float2 qbv[2];
#pragma unroll
        for (int j = 0; j < 2; ++j)
            qbv[j] = *(const float2*)(g_qb + b * HWQ + n0 + 2 * (tx + 16 * j));
        float2 s[2] = {{0.f, 0.f}, {0.f, 0.f}};
#pragma unroll
        for (int i = 0; i < 8; ++i) {
            int m = m0 + ty + 16 * i;
#pragma unroll
            for (int j = 0; j < 2; ++j) {
                float2 v = *reinterpret_cast<float2*>(&acc[i][j]);
                v.x = __expf(v.x - qbv[j].x);
                v.y = __expf(v.y - qbv[j].y);
                int n = n0 + 2 * (tx + 16 * j);
                *(float2*)(Cg + (size_t)m * N + n) = v;
                s[j].x += v.x; s[j].y += v.y;
            }
        }
        red[tid][0] = s[0];
        red[tid][1] = s[1];
        __syncthreads();
        if (ty == 0) {
            float2 t0 = {0.f, 0.f}, t1 = {0.f, 0.f};
#pragma unroll
            for (int r = 0; r < 16; ++r) {
                float2 a0 = red[r * 16 + tx][0], a1 = red[r * 16 + tx][1];
                t0.x += a0.x; t0.y += a0.y;
                t1.x += a1.x; t1.y += a1.y;
            }
            float* sm = g_sums + b * HWQ;
            atomicAdd(sm + n0 + 2 * tx,            t0.x);
            atomicAdd(sm + n0 + 2 * tx + 1,        t0.y);
            atomicAdd(sm + n0 + 2 * (tx + 16),     t1.x);
            atomicAdd(sm + n0 + 2 * (tx + 16) + 1, t1.y);
        }
    } else {
        // transposed store: C[n][m] -> g_U[j][q]
#pragma unroll
        for (int i = 0; i < 8; ++i) {
            int m = m0 + ty + 16 * i;
#pragma unroll
            for (int j = 0; j < 2; ++j) {
                int n = n0 + 2 * (tx + 16 * j);
                float2 v = *reinterpret_cast<float2*>(&acc[i][j]);
                Cg[(size_t)n * M + m]       = v.x;
                Cg[(size_t)(n + 1) * M + m] = v.y;
            }
        }
    }
}

// ---------------- invs = 1/sums ----------------
__global__ void recip_kernel() {
    int i = blockIdx.x * blockDim.x + threadIdx.x;
    if (i < NB * HWQ) g_invs[i] = 1.0f / g_sums[i];
}

// ---------------- parity-plane gather: U -> out ----------------
__global__ void gather_out(float* __restrict__ out) {
    int ox = blockIdx.x * blockDim.x + threadIdx.x;
    if (ox >= OH) return;
    int oy = blockIdx.y;
    int bc = blockIdx.z;
    int b = bc >> 6, c = bc & 63;

    int ys[2], tys[2], ny;
    if (oy & 1) { ny = 2; ys[0] = (oy - 1) >> 1; tys[0] = 2; ys[1] = (oy + 1) >> 1; tys[1] = 0; }
    else        { ny = 1; ys[0] = oy >> 1; tys[0] = 1; }
    int xs[2], txs[2], nx;
    if (ox & 1) { nx = 2; xs[0] = (ox - 1) >> 1; txs[0] = 2; xs[1] = (ox + 1) >> 1; txs[1] = 0; }
    else        { nx = 1; xs[0] = ox >> 1; txs[0] = 1; }

    const float* Ub = g_U + (size_t)b * VF * HWQ;
    const float* is = g_invs + b * HWQ;
    float acc = 0.f;
    for (int iy = 0; iy < ny; ++iy)
        for (int ix = 0; ix < nx; ++ix) {
            int q = ys[iy] * WW + xs[ix];
            int t = tys[iy] * 3 + txs[ix];
            acc = fmaf(Ub[(size_t)(t * 64 + c) * HWQ + q], is[q], acc);
        }
    out[(((size_t)b * CIN + c) * OH + oy) * OH + ox] = acc;
}

// ---------------- launch ----------------
extern "C" void kernel_launch(void* const* d_in, const int* in_sizes, int n_in,
                              void* d_out, int out_size) {
    const float* input = (const float*)d_in[0];
    const float* small = (const float*)d_in[1];
    const float* w1 = (const float*)d_in[2];
    const float* b1 = (const float*)d_in[3];
    const float* a1 = (const float*)d_in[4];
    const float* w2 = (const float*)d_in[5];
    const float* b2 = (const float*)d_in[6];
    const float* a2 = (const float*)d_in[7];
    const float* wa = (const float*)d_in[8];
    const float* ba = (const float*)d_in[9];
    const float* aa = (const float*)d_in[10];
    float* out = (float*)d_out;

    // ordered so gemm_kernel<1> is launch #6 (ncu -s 5 -c 1 captures it)
    conv1x1_prelu<0><<<dim3(HWQ / 256, CR,  NB), 256>>>(input, w1, b1, a1);   // 1
    conv1x1_prelu<2><<<dim3(LKEY / 256, CR,  NB), 256>>>(small, w2, b2, a2);  // 2
    build_Q <<<dim3(HWQ / 256, KF, NB), 256>>>();                             // 3
    build_KT<<<dim3(LKEY / 128, NB), 128>>>();                                // 4
    qbound_kernel<<<dim3(HWQ / 256, NB), 256>>>();                            // 5
    gemm_kernel<1><<<dim3(HWQ / 64, LKEY / 128, NB), 256>>>();                // 6 <- profiled
    conv1x1_prelu<1><<<dim3(LKEY / 256, CIN, NB), 256>>>(small, wa, ba, aa);  // 7
    build_V <<<dim3(LKEY, NB), 64>>>();                                       // 8
    recip_kernel<<<(NB * HWQ + 255) / 256, 256>>>();                          // 9
    gemm_kernel<2><<<dim3(VF / 64, HWQ / 128, NB), 256>>>();                  // 10
    gather_out<<<dim3((OH + 127) / 128, OH, NB * CIN), 128>>>(out);           // 11
}

// round 11
// speedup vs baseline: 1.7651x; 1.4276x over previous
#include <cuda_runtime.h>
#include <cuda_bf16.h>
#include <math.h>

// ---------------- problem constants ----------------
#define NB    4
#define CIN   64
#define CR    32
#define HH    96
#define WW    96
#define HWQ   (HH*WW)        // 9216 queries per sample
#define HS    48
#define WS    48
#define LKEY  (HS*WS)        // 2304 keys per sample
#define KF    (CR*9)         // 288 q/k feature dim
#define VF    (CIN*9)        // 576 value dim (j = tap*64 + c)
#define OH    191

// ---------------- scratch (device globals; allocation-free) ----------------
__device__ float g_match[(size_t)NB*CR*98*98];          // padded match_input
__device__ float g_embed[(size_t)NB*CIN*50*50];         // padded embed_w
__device__ float g_ref  [(size_t)NB*CR*50*50];          // padded ref
__device__ float g_Q [(size_t)NB*KF*HWQ];               // [b][f][q]
__device__ float g_KT[(size_t)NB*KF*LKEY];              // [b][f][l]  (SCALE/norm folded)
__device__ float g_V [(size_t)NB*LKEY*VF];              // [b][l][j]  (/6 folded)
__device__ float g_S [(size_t)NB*LKEY*HWQ];             // exp(logit - qb)  (340MB)
__device__ float g_U [(size_t)NB*VF*HWQ];               // [b][j][q]
__device__ float g_qb  [NB*HWQ];                        // 10*||q_patch||
__device__ float g_sums[NB*HWQ];                        // column sums of exp
__device__ float g_invs[NB*HWQ];

// ---------------- helpers ----------------
__device__ __forceinline__ void fma2(unsigned long long& d,
                                     unsigned long long a,
                                     unsigned long long b) {
    asm("fma.rn.f32x2 %0, %1, %2, %0;" : "+l"(d) : "l"(a), "l"(b));
}
__device__ __forceinline__ unsigned long long dup2(float a) {
    unsigned long long r;
    asm("mov.b64 %0, {%1, %1};" : "=l"(r) : "f"(a));
    return r;
}

// ---------------- conv1x1 + prelu body (borders zeroed in-kernel) ----------
// SEL 0: input -> g_match (Cout=32, 96x96 -> 98x98), also zeroes g_sums
// SEL 1: small -> g_embed (Cout=64, 48x48 -> 50x50)
// SEL 2: small -> g_ref   (Cout=32, 48x48 -> 50x50)
template<int SEL>
__device__ __forceinline__ void conv_body(int bx, const float* __restrict__ in,
                                          const float* __restrict__ w,
                                          const float* __restrict__ bias,
                                          const float* __restrict__ a) {
    constexpr int HWd  = (SEL == 0) ? HWQ : LKEY;
    constexpr int Wd   = (SEL == 0) ? WW : WS;
    constexpr int Wp   = (SEL == 0) ? 98 : 50;
    constexpr int Cout = (SEL == 1) ? CIN : CR;
    constexpr int NBORD = (SEL == 0) ? 388 : 196;  // Wp*Wp - Wd*Wd
    float* outp = (SEL == 0) ? g_match : ((SEL == 1) ? g_embed : g_ref);

    int px = bx * 256 + threadIdx.x;
    int co = blockIdx.y, b = blockIdx.z;
    float* plane = outp + (size_t)(b * Cout + co) * Wp * Wp;

    if (px < NBORD) {
        int by, bxx;
        if (px < Wp)            { by = 0;             bxx = px; }
        else if (px < 2*Wp)     { by = Wp - 1;        bxx = px - Wp; }
        else if (px < 2*Wp+Wd)  { by = px - 2*Wp + 1; bxx = 0; }
        else                    { by = px - (2*Wp+Wd) + 1; bxx = Wp - 1; }
        plane[by * Wp + bxx] = 0.f;
    }
    if (SEL == 0 && co == 0) g_sums[b * HWQ + px] = 0.f;

    const float* ip = in + (size_t)b * CIN * HWd + px;
    const float* wp = w + co * CIN;
    float s = bias[co];
#pragma unroll 16
    for (int ci = 0; ci < CIN; ++ci) s = fmaf(ip[(size_t)ci * HWd], wp[ci], s);
    float al = a[0];
    s = (s >= 0.f) ? s : al * s;
    int y = px / Wd, x = px - y * Wd;
    plane[(y + 1) * Wp + (x + 1)] = s;
}

// fused SEL0 + SEL2 (independent; one launch)
__global__ void conv_fused(const float* __restrict__ input,
                           const float* __restrict__ small,
                           const float* __restrict__ w1, const float* __restrict__ b1,
                           const float* __restrict__ a1,
                           const float* __restrict__ w2, const float* __restrict__ b2,
                           const float* __restrict__ a2) {
    if (blockIdx.x < 36) conv_body<0>(blockIdx.x, input, w1, b1, a1);
    else                 conv_body<2>(blockIdx.x - 36, small, w2, b2, a2);
}

__global__ void conv1_kernel(const float* __restrict__ small,
                             const float* __restrict__ wa, const float* __restrict__ ba,
                             const float* __restrict__ aa) {
    conv_body<1>(blockIdx.x, small, wa, ba, aa);
}

// ---------------- fused build_Q + qbound ----------------
// blockIdx.y < KF: Q[b][f][q];  blockIdx.y == KF: qb = 10*||q_patch||
__global__ void build_Qqb() {
    int m = blockIdx.x * 256 + threadIdx.x;            // 9216
    int b = blockIdx.z;
    int y = m / WW, x = m - y * WW;
    if (blockIdx.y < KF) {
        int f = blockIdx.y;
        int c = f / 9, t = f - 9 * c;
        g_Q[((size_t)b * KF + f) * HWQ + m] =
            g_match[(((size_t)b * CR + c) * 98 + y + t / 3) * 98 + x + t % 3];
    } else {
        const float* base = g_match + (size_t)b * CR * 98 * 98;
        float ss = 0.f;
        for (int c = 0; c < CR; ++c) {
            const float* p = base + ((size_t)c * 98 + y) * 98 + x;
#pragma unroll
            for (int t = 0; t < 9; ++t) {
                float v = p[(t / 3) * 98 + (t % 3)];
                ss = fmaf(v, v, ss);
            }
        }
        g_qb[b * HWQ + m] = 10.0f * sqrtf(ss);
    }
}

// ---------------- build K^T: [b][f][l], normalized, x SCALE ----------------
__global__ void build_KT() {
    int l = blockIdx.x * blockDim.x + threadIdx.x;     // 2304
    int b = blockIdx.y;
    int ly = l / WS, lx = l - WS * ly;
    const float* base = g_ref + (size_t)b * CR * 2500;
    float ss = 0.f;
    for (int c = 0; c < CR; ++c) {
#pragma unroll
        for (int t = 0; t < 9; ++t) {
            float v = base[((size_t)c * 50 + ly + t / 3) * 50 + lx + t % 3];
            ss = fmaf(v, v, ss);
        }
    }
    float sc = 10.0f / fmaxf(sqrtf(ss), 1e-4f);        // SCALE / max(norm, EPS)
    for (int c = 0; c < CR; ++c) {
#pragma unroll
        for (int t = 0; t < 9; ++t) {
            float v = base[((size_t)c * 50 + ly + t / 3) * 50 + lx + t % 3];
            g_KT[((size_t)b * KF + (c * 9 + t)) * LKEY + l] = v * sc;
        }
    }
}

// ---------------- build V: [b][l][t*64+c], /6 folded ----------------
__global__ void build_V() {
    int c = threadIdx.x;                               // 64
    int l = blockIdx.x, b = blockIdx.y;
    int ly = l / WS, lx = l - WS * ly;
    const float* base = g_embed + ((size_t)b * CIN + c) * 2500;
    float* vp = g_V + ((size_t)b * LKEY + l) * VF;
#pragma unroll
    for (int t = 0; t < 9; ++t)
        vp[t * 64 + c] = base[(ly + t / 3) * 50 + lx + t % 3] * (1.0f / 6.0f);
}

// ---------------- FFMA2 tiled GEMM, 128x64 tile, BK=32 --------------------
// A stored as SCALARS in smem (kk-major); duplication into (a,a) pairs done
// in registers (mov.b64) -> smem traffic 48B/thread/kk instead of 80B.
// PHASE 1: C[m][n] = KT^T x Q : A[K=288][M=2304], B[288][N=9216] -> exp -> g_S
// PHASE 2: C[n][m] = S^T x V  : A[K=2304][M=9216], B[2304][N=576] -> g_U [j][q]
#define ASTR 132    // 128 m + 4 pad (multiple of 4 floats for STS.128)
#define BSTR 68
template<int PHASE>
__global__ __launch_bounds__(256, 2) void gemm_kernel() {
    constexpr int M = (PHASE == 1) ? LKEY : HWQ;
    constexpr int N = (PHASE == 1) ? HWQ  : VF;
    constexpr int K = (PHASE == 1) ? KF   : LKEY;
    const float* __restrict__ Abase = (PHASE == 1) ? g_KT : g_S;
    const float* __restrict__ Bbase = (PHASE == 1) ? g_Q  : g_V;
    float* __restrict__ Cbase       = (PHASE == 1) ? g_S  : g_U;

    __shared__ float As[32 * ASTR];     // kk-major scalars
    __shared__ float Bs[32 * BSTR];     // kk-major, n contiguous
    __shared__ float2 red[256][2];      // phase-1 column-sum reduction

    int b = blockIdx.z;
    const float* Ag = Abase + (size_t)b * K * M;
    const float* Bg = Bbase + (size_t)b * K * N;
    int n0 = blockIdx.x * 64, m0 = blockIdx.y * 128;
    int tid = threadIdx.x;
    int tx = tid & 15, ty = tid >> 4;   // thread tile: m = m0+ty*8+r (8), n = n0+2(tx+16j) (2 pairs)

    int lk = tid >> 3, lc = tid & 7;    // loaders: 32 k-rows x 8 col-groups

    unsigned long long acc[8][2];
#pragma unroll
    for (int i = 0; i < 8; ++i) { acc[i][0] = 0ull; acc[i][1] = 0ull; }

    float4 ra[4], rb[2];

    // prologue: tile 0
#pragma unroll
    for (int p = 0; p < 4; ++p)
        ra[p] = *(const float4*)(Ag + (size_t)lk * M + m0 + (lc + 8 * p) * 4);
#pragma unroll
    for (int p = 0; p < 2; ++p)
        rb[p] = *(const float4*)(Bg + (size_t)lk * N + n0 + (lc + 8 * p) * 4);
#pragma unroll
    for (int p = 0; p < 4; ++p)
        *(float4*)(As + lk * ASTR + (lc + 8 * p) * 4) = ra[p];
#pragma unroll
    for (int p = 0; p < 2; ++p)
        *(float4*)(Bs + lk * BSTR + (lc + 8 * p) * 4) = rb[p];
    __syncthreads();

    for (int kt = 0; kt < K; kt += 32) {
        if (kt + 32 < K) {
#pragma unroll
            for (int p = 0; p < 4; ++p)
                ra[p] = *(const float4*)(Ag + (size_t)(kt + 32 + lk) * M + m0 + (lc + 8 * p) * 4);
#pragma unroll
            for (int p = 0; p < 2; ++p)
                rb[p] = *(const float4*)(Bg + (size_t)(kt + 32 + lk) * N + n0 + (lc + 8 * p) * 4);
        }
#pragma unroll
        for (int kk = 0; kk < 32; ++kk) {
            const float* ar = As + kk * ASTR + ty * 8;
            float4 a0 = *(const float4*)(ar);
            float4 a1 = *(const float4*)(ar + 4);
            unsigned long long bv0 = *(const unsigned long long*)(Bs + kk * BSTR + 2 * tx);
            unsigned long long bv1 = *(const unsigned long long*)(Bs + kk * BSTR + 2 * (tx + 16));
            unsigned long long pa;
            pa = dup2(a0.x); fma2(acc[0][0], pa, bv0); fma2(acc[0][1], pa, bv1);
            pa = dup2(a0.y); fma2(acc[1][0], pa, bv0); fma2(acc[1][1], pa, bv1);
            pa = dup2(a0.z); fma2(acc[2][0], pa, bv0); fma2(acc[2][1], pa, bv1);
            pa = dup2(a0.w); fma2(acc[3][0], pa, bv0); fma2(acc[3][1], pa, bv1);
            pa = dup2(a1.x); fma2(acc[4][0], pa, bv0); fma2(acc[4][1], pa, bv1);
            pa = dup2(a1.y); fma2(acc[5][0], pa, bv0); fma2(acc[5][1], pa, bv1);
            pa = dup2(a1.z); fma2(acc[6][0], pa, bv0); fma2(acc[6][1], pa, bv1);
            pa = dup2(a1.w); fma2(acc[7][0], pa, bv0); fma2(acc[7][1], pa, bv1);
        }
        if (kt + 32 < K) {
            __syncthreads();
#pragma unroll
            for (int p = 0; p < 4; ++p)
                *(float4*)(As + lk * ASTR + (lc + 8 * p) * 4) = ra[p];
#pragma unroll
            for (int p = 0; p < 2; ++p)
                *(float4*)(Bs + lk * BSTR + (lc + 8 * p) * 4) = rb[p];
            __syncthreads();
        }
    }

    float* Cg = Cbase + (size_t)b * M * N;
    if (PHASE == 1) {
        // exp(logit - qb), store, and column-sum via smem reduce + atomics
        float2 qbv[2];
#pragma unroll
        for (int j = 0; j < 2; ++j)
            qbv[j] = *(const float2*)(g_qb + b * HWQ + n0 + 2 * (tx + 16 * j));
        float2 s[2] = {{0.f, 0.f}, {0.f, 0.f}};
#pragma unroll
        for (int i = 0; i < 8; ++i) {
            int m = m0 + ty * 8 + i;
#pragma unroll
            for (int j = 0; j < 2; ++j) {
                float2 v = *reinterpret_cast<float2*>(&acc[i][j]);
                v.x = __expf(v.x - qbv[j].x);
                v.y = __expf(v.y - qbv[j].y);
                int n = n0 + 2 * (tx + 16 * j);
                *(float2*)(Cg + (size_t)m * N + n) = v;
                s[j].x += v.x; s[j].y += v.y;
            }
        }
        red[tid][0] = s[0];
        red[tid][1] = s[1];
        __syncthreads();
        if (ty == 0) {
            float2 t0 = {0.f, 0.f}, t1 = {0.f, 0.f};
#pragma unroll
            for (int r = 0; r < 16; ++r) {
                float2 a0 = red[r * 16 + tx][0], a1 = red[r * 16 + tx][1];
                t0.x += a0.x; t0.y += a0.y;
                t1.x += a1.x; t1.y += a1.y;
            }
            float* sm = g_sums + b * HWQ;
            atomicAdd(sm + n0 + 2 * tx,            t0.x);
            atomicAdd(sm + n0 + 2 * tx + 1,        t0.y);
            atomicAdd(sm + n0 + 2 * (tx + 16),     t1.x);
            atomicAdd(sm + n0 + 2 * (tx + 16) + 1, t1.y);
        }
    } else {
        // transposed store: per n-column, thread's 8 consecutive m -> 2x float4
#pragma unroll
        for (int j = 0; j < 2; ++j) {
            int n = n0 + 2 * (tx + 16 * j);
            float2 w[8];
#pragma unroll
            for (int i = 0; i < 8; ++i) w[i] = *reinterpret_cast<float2*>(&acc[i][j]);
            size_t base0 = (size_t)n * M + m0 + ty * 8;
            *(float4*)(Cg + base0)     = make_float4(w[0].x, w[1].x, w[2].x, w[3].x);
            *(float4*)(Cg + base0 + 4) = make_float4(w[4].x, w[5].x, w[6].x, w[7].x);
            size_t base1 = (size_t)(n + 1) * M + m0 + ty * 8;
            *(float4*)(Cg + base1)     = make_float4(w[0].y, w[1].y, w[2].y, w[3].y);
            *(float4*)(Cg + base1 + 4) = make_float4(w[4].y, w[5].y, w[6].y, w[7].y);
        }
    }
}

// ---------------- invs = 1/sums ----------------
__global__ void recip_kernel() {
    int i = blockIdx.x * blockDim.x + threadIdx.x;
    if (i < NB * HWQ) g_invs[i] = 1.0f / g_sums[i];
}

// ---------------- parity-plane gather: U -> out ----------------
__global__ void gather_out(float* __restrict__ out) {
    int ox = blockIdx.x * blockDim.x + threadIdx.x;
    if (ox >= OH) return;
    int oy = blockIdx.y;
    int bc = blockIdx.z;
    int b = bc >> 6, c = bc & 63;

    int ys[2], tys[2], ny;
    if (oy & 1) { ny = 2; ys[0] = (oy - 1) >> 1; tys[0] = 2; ys[1] = (oy + 1) >> 1; tys[1] = 0; }
    else        { ny = 1; ys[0] = oy >> 1; tys[0] = 1; }
    int xs[2], txs[2], nx;
    if (ox & 1) { nx = 2; xs[0] = (ox - 1) >> 1; txs[0] = 2; xs[1] = (ox + 1) >> 1; txs[1] = 0; }
    else        { nx = 1; xs[0] = ox >> 1; txs[0] = 1; }

    const float* Ub = g_U + (size_t)b * VF * HWQ;
    const float* is = g_invs + b * HWQ;
    float acc = 0.f;
    for (int iy = 0; iy < ny; ++iy)
        for (int ix = 0; ix < nx; ++ix) {
            int q = ys[iy] * WW + xs[ix];
            int t = tys[iy] * 3 + txs[ix];
            acc = fmaf(Ub[(size_t)(t * 64 + c) * HWQ + q], is[q], acc);
        }
    out[(((size_t)b * CIN + c) * OH + oy) * OH + ox] = acc;
}

// ---------------- launch ----------------
extern "C" void kernel_launch(void* const* d_in, const int* in_sizes, int n_in,
                              void* d_out, int out_size) {
    const float* input = (const float*)d_in[0];
    const float* small = (const float*)d_in[1];
    const float* w1 = (const float*)d_in[2];
    const float* b1 = (const float*)d_in[3];
    const float* a1 = (const float*)d_in[4];
    const float* w2 = (const float*)d_in[5];
    const float* b2 = (const float*)d_in[6];
    const float* a2 = (const float*)d_in[7];
    const float* wa = (const float*)d_in[8];
    const float* ba = (const float*)d_in[9];
    const float* aa = (const float*)d_in[10];
    float* out = (float*)d_out;

    // gemm_kernel<1> is my launch #4 = global #6 (harness adds 2) -> profiled
    conv_fused<<<dim3(45, 32, NB), 256>>>(input, small, w1, b1, a1, w2, b2, a2); // 1
    build_Qqb<<<dim3(36, KF + 1, NB), 256>>>();                                  // 2
    build_KT<<<dim3(LKEY / 128, NB), 128>>>();                                   // 3
    gemm_kernel<1><<<dim3(HWQ / 64, LKEY / 128, NB), 256>>>();                   // 4 <- profiled
    conv1_kernel<<<dim3(LKEY / 256, CIN, NB), 256>>>(small, wa, ba, aa);         // 5
    build_V<<<dim3(LKEY, NB), 64>>>();                                           // 6
    recip_kernel<<<(NB * HWQ + 255) / 256, 256>>>();                             // 7
    gemm_kernel<2><<<dim3(VF / 64, HWQ / 128, NB), 256>>>();                     // 8
    gather_out<<<dim3((OH + 127) / 128, OH, NB * CIN), 128>>>(out);              // 9
}